// round 17
// baseline (speedup 1.0000x reference)
#include <cuda_runtime.h>
#include <cuda_bf16.h>
#include <cuda_fp16.h>
#include <math.h>
#include <stdint.h>

#define B_    4
#define N_    8192
#define C_    512
#define H_    8
#define D_    64
#define M_    64           // window
#define NW    (N_ / M_)    // 128
#define ROWS  (B_ * N_)    // 32768
#define NEG_INF_F (-1000000000.0f)

// ---------------- scratch (static device globals: allocation-free) ------------
__device__ __align__(16) __half g_xh[(size_t)ROWS * C_];     // fp16 x
__device__ __align__(16) __half g_attnH[(size_t)ROWS * C_];  // fp16 attn (B,N,C)
__device__ __align__(16) __half g_W16[1024 * C_];            // fp16 Wq | Wkv
__device__ __align__(16) __half g_Wp16[C_ * C_];             // fp16 Wproj
__device__ __align__(16) __half g_Qh[(size_t)ROWS * 256];    // fp16 q, local heads
__device__ __align__(16) __half g_KVh[(size_t)ROWS * 256];   // fp16 kv, local heads
__device__ __align__(16) __half g_QhL[(size_t)ROWS * 256];   // fp16 q, linear heads
__device__ __align__(16) __half g_KVhL[(size_t)ROWS * 256];  // fp16 kv, linear heads
__device__ float g_ctx[16 * 64 * 64];
__device__ float g_csum[16 * 64];

// ---------------- helpers -----------------------------------------------------
__device__ __forceinline__ uint32_t smem_u32(const void* p) {
    uint32_t a;
    asm("{ .reg .u64 t; cvta.to.shared.u64 t, %1; cvt.u32.u64 %0, t; }"
        : "=r"(a) : "l"(p));
    return a;
}
#define CP_ASYNC16(dst, src) \
    asm volatile("cp.async.cg.shared.global [%0], [%1], 16;" \
                 :: "r"(dst), "l"(src))
#define CP_COMMIT() asm volatile("cp.async.commit_group;" ::: "memory")
#define CP_WAIT2()  asm volatile("cp.async.wait_group 2;" ::: "memory")

__device__ __forceinline__ void ldsm_x4(uint32_t& r0, uint32_t& r1,
                                        uint32_t& r2, uint32_t& r3, uint32_t addr) {
    asm volatile("ldmatrix.sync.aligned.m8n8.x4.shared.b16 {%0,%1,%2,%3}, [%4];"
                 : "=r"(r0), "=r"(r1), "=r"(r2), "=r"(r3) : "r"(addr));
}
__device__ __forceinline__ void ldsm_x4_trans(uint32_t& r0, uint32_t& r1,
                                              uint32_t& r2, uint32_t& r3,
                                              uint32_t addr) {
    asm volatile("ldmatrix.sync.aligned.m8n8.x4.trans.shared.b16 {%0,%1,%2,%3}, [%4];"
                 : "=r"(r0), "=r"(r1), "=r"(r2), "=r"(r3) : "r"(addr));
}
__device__ __forceinline__ void mma_f16(float* c, uint32_t a0, uint32_t a1,
                                        uint32_t a2, uint32_t a3,
                                        uint32_t b0, uint32_t b1) {
    asm volatile(
        "mma.sync.aligned.m16n8k16.row.col.f32.f16.f16.f32 "
        "{%0,%1,%2,%3}, {%4,%5,%6,%7}, {%8,%9}, {%0,%1,%2,%3};"
        : "+f"(c[0]), "+f"(c[1]), "+f"(c[2]), "+f"(c[3])
        : "r"(a0), "r"(a1), "r"(a2), "r"(a3), "r"(b0), "r"(b1));
}
__device__ __forceinline__ uint32_t pack_h2(float lo, float hi) {
    __half2 h = __floats2half2_rn(lo, hi);
    return *reinterpret_cast<uint32_t*>(&h);
}

// ---------------- conversions --------------------------------------------------
__global__ __launch_bounds__(256) void round_h_kernel(
    const float* __restrict__ src, __half* __restrict__ dst, int nrows)
{
    int total = nrows * (C_ / 4);
    for (int i = blockIdx.x * blockDim.x + threadIdx.x; i < total;
         i += gridDim.x * blockDim.x) {
        int r = i >> 7;
        int c = (i & 127) * 4;
        float4 v = *(const float4*)(src + (size_t)r * C_ + c);
        __half* base = dst + (size_t)r * C_ + c;
        *(__half2*)(base + 0) = __floats2half2_rn(v.x, v.y);
        *(__half2*)(base + 2) = __floats2half2_rn(v.z, v.w);
    }
}

// weights (3 matrices, 512x512 each = 65536 quads) + ctx/csum zeroing
__global__ __launch_bounds__(256) void prep_kernel(
    const float* __restrict__ Wq, const float* __restrict__ Wkv,
    const float* __restrict__ Wproj)
{
    const int wtotal = 3 * 65536;
    const int total = wtotal + 16 * 4096 + 16 * 64;
    for (int i = blockIdx.x * blockDim.x + threadIdx.x; i < total;
         i += gridDim.x * blockDim.x) {
        if (i < wtotal) {
            int mat = i >> 16, wi = i & 65535;
            int r = wi >> 7, c = (wi & 127) * 4;
            const float* src = (mat == 0) ? Wq : (mat == 1) ? Wkv : Wproj;
            __half* dst = (mat == 0) ? g_W16
                        : (mat == 1) ? (g_W16 + (size_t)512 * C_) : g_Wp16;
            float4 v = *(const float4*)(src + (size_t)r * C_ + c);
            __half* base = dst + (size_t)r * C_ + c;
            *(__half2*)(base + 0) = __floats2half2_rn(v.x, v.y);
            *(__half2*)(base + 2) = __floats2half2_rn(v.z, v.w);
        } else if (i < wtotal + 65536) {
            g_ctx[i - wtotal] = 0.f;
        } else {
            g_csum[i - wtotal - 65536] = 0.f;
        }
    }
}

// ---------------- fp16 mma GEMM, K=512, 128x256 tile --------------------------
#define GST     4
#define GA_ST   (128 * 40)
#define GB_ST   (256 * 40)
#define GB_BASE (GST * GA_ST)
#define GEMM_SMEM ((GB_BASE + GST * GB_ST) * 2)
#define KITS    (C_ / 32)             // 16

__global__ __launch_bounds__(512, 1) void gemm_f16(
    const __half* __restrict__ Ah, const __half* __restrict__ Bh,
    float* __restrict__ fy,
    __half* __restrict__ o0, __half* __restrict__ o1,
    __half* __restrict__ o2, __half* __restrict__ o3,
    const float* __restrict__ bias, int mode)
{
    extern __shared__ __half smh[];
    const int tid = threadIdx.x;
    const int warp = tid >> 5, lane = tid & 31;
    const int wm = warp & 3, wn = warp >> 2;
    const int m0 = blockIdx.y * 128;
    const int n0 = blockIdx.x * 256;

    float acc[2][8][4];
#pragma unroll
    for (int i = 0; i < 2; i++)
#pragma unroll
        for (int j = 0; j < 8; j++)
#pragma unroll
            for (int e = 0; e < 4; e++) acc[i][j][e] = 0.f;

    const __half* Ab = Ah + (size_t)m0 * C_;
    const __half* Bb = Bh + (size_t)n0 * C_;

    const int lrow = tid >> 2;
    const int lchk = (tid & 3) * 8;

#define LOADQ(s, j) do { \
    const int ko = (j) * 32; \
    CP_ASYNC16(smem_u32(smh + (s) * GA_ST + lrow * 40 + lchk), \
               Ab + (size_t)lrow * C_ + ko + lchk); \
    CP_ASYNC16(smem_u32(smh + GB_BASE + (size_t)(s) * GB_ST + lrow * 40 + lchk), \
               Bb + (size_t)lrow * C_ + ko + lchk); \
    CP_ASYNC16(smem_u32(smh + GB_BASE + (size_t)(s) * GB_ST + (lrow + 128) * 40 + lchk), \
               Bb + (size_t)(lrow + 128) * C_ + ko + lchk); \
} while (0)

    LOADQ(0, 0); CP_COMMIT();
    LOADQ(1, 1); CP_COMMIT();
    LOADQ(2, 2); CP_COMMIT();

    const int a_row = wm * 32 + (lane & 15);
    const int a_col = (lane >> 4) << 3;
    const int b_row = wn * 64 + ((lane >> 4) << 3) + (lane & 7);
    const int b_col = ((lane >> 3) & 1) << 3;

    for (int j = 0; j < KITS; ++j) {
        const int s = j & 3;
        CP_WAIT2();
        __syncthreads();
        if (j + 3 < KITS) LOADQ((j + 3) & 3, j + 3);
        CP_COMMIT();

        const __half* As = smh + s * GA_ST;
        const __half* Bs = smh + GB_BASE + (size_t)s * GB_ST;
#pragma unroll
        for (int kk = 0; kk < 2; kk++) {
            const int k16 = kk * 16;
            uint32_t a[2][4];
#pragma unroll
            for (int i = 0; i < 2; i++)
                ldsm_x4(a[i][0], a[i][1], a[i][2], a[i][3],
                        smem_u32(As + (a_row + i * 16) * 40 + k16 + a_col));
            uint32_t b[4][4];
#pragma unroll
            for (int jb = 0; jb < 4; jb++)
                ldsm_x4(b[jb][0], b[jb][1], b[jb][2], b[jb][3],
                        smem_u32(Bs + (b_row + jb * 16) * 40 + k16 + b_col));
#pragma unroll
            for (int i = 0; i < 2; i++)
#pragma unroll
                for (int jn = 0; jn < 8; jn++) {
                    const int jb = jn >> 1, hf = (jn & 1) * 2;
                    mma_f16(acc[i][jn], a[i][0], a[i][1], a[i][2], a[i][3],
                            b[jb][hf], b[jb][hf + 1]);
                }
        }
    }

    if (mode == 0) {
        __half* Hd = (blockIdx.x == 0) ? o0 : (blockIdx.x == 1) ? o1
                   : (blockIdx.x == 2) ? o2 : o3;
#pragma unroll
        for (int i = 0; i < 2; i++) {
            const int r0 = m0 + wm * 32 + i * 16 + (lane >> 2);
#pragma unroll
            for (int jn = 0; jn < 8; jn++) {
                const int c0 = wn * 64 + jn * 8 + (lane & 3) * 2;
                *(__half2*)(Hd + (size_t)r0 * 256 + c0) =
                    __floats2half2_rn(acc[i][jn][0], acc[i][jn][1]);
                *(__half2*)(Hd + (size_t)(r0 + 8) * 256 + c0) =
                    __floats2half2_rn(acc[i][jn][2], acc[i][jn][3]);
            }
        }
    } else {
#pragma unroll
        for (int i = 0; i < 2; i++) {
            const int r0 = m0 + wm * 32 + i * 16 + (lane >> 2);
#pragma unroll
            for (int jn = 0; jn < 8; jn++) {
                const int c0 = n0 + wn * 64 + jn * 8 + (lane & 3) * 2;
                float b0 = bias[c0], b1 = bias[c0 + 1];
                *(float2*)(fy + (size_t)r0 * C_ + c0) =
                    make_float2(acc[i][jn][0] + b0, acc[i][jn][1] + b1);
                *(float2*)(fy + (size_t)(r0 + 8) * C_ + c0) =
                    make_float2(acc[i][jn][2] + b0, acc[i][jn][3] + b1);
            }
        }
    }
}

// ---------------- local window attention via mma (heads 0..3) ------------------
#define QS2 72          // halfs: 64 + 8
#define KS2 72
#define OA2 36          // floats: 32 + 4
#define OFF_QS 0
#define OFF_KS (OFF_QS + 64 * QS2 * 2)        // 9216
#define OFF_OA (OFF_KS + 192 * KS2 * 2)       // 36864
#define OFF_RED (OFF_OA + 64 * OA2 * 4)       // 46080
#define OFF_SUM (OFF_RED + 512)               // 46592
#define LA_SMEM (OFF_SUM + 512)               // 47104

__global__ __launch_bounds__(256, 2) void local_attn_mma(float* __restrict__ attn_out)
{
    extern __shared__ char smla[];
    __half* qs = (__half*)(smla + OFF_QS);
    __half* ks = (__half*)(smla + OFF_KS);
    float* oacc = (float*)(smla + OFF_OA);
    float* redbuf = (float*)(smla + OFF_RED);
    float* sumbuf = (float*)(smla + OFF_SUM);

    const int w = blockIdx.x;
    const int bh = blockIdx.y;
    const int b = bh >> 2, hh = bh & 3;
    const int t = threadIdx.x;
    const int warp = t >> 5, lane = t & 31;
    const int wm = warp & 3, wn = warp >> 2;
    const size_t rowbase = (size_t)b * N_ + (size_t)w * M_;
    const int col0h = hh * D_;

    {
        const __half2 sc = __floats2half2_rn(0.125f, 0.125f);
        for (int idx = t; idx < 64 * 8; idx += 256) {
            int r = idx >> 3, c8 = (idx & 7) * 8;
            uint4 v = *(const uint4*)(g_Qh + (rowbase + r) * 256 + col0h + c8);
            __half2* hv = (__half2*)&v;
            hv[0] = __hmul2(hv[0], sc); hv[1] = __hmul2(hv[1], sc);
            hv[2] = __hmul2(hv[2], sc); hv[3] = __hmul2(hv[3], sc);
            *(uint4*)(qs + r * QS2 + c8) = v;
        }
    }
    const int nbase = (w - 1) * M_;
    for (int idx = t; idx < 192 * 8; idx += 256) {
        int j = idx >> 3, c8 = (idx & 7) * 8;
        int n = nbase + j;
        uint4 v = make_uint4(0, 0, 0, 0);
        if (n >= 0 && n < N_)
            v = *(const uint4*)(g_KVh + ((size_t)b * N_ + n) * 256 + col0h + c8);
        *(uint4*)(ks + j * KS2 + c8) = v;
    }
    __syncthreads();

    float c[12][4];
#pragma unroll
    for (int jn = 0; jn < 12; jn++)
#pragma unroll
        for (int e = 0; e < 4; e++) c[jn][e] = 0.f;

    const int a_rw = wm * 16 + (lane & 15);
    const int a_cl = (lane >> 4) << 3;
    const int b_rw = wn * 96 + ((lane >> 4) << 3) + (lane & 7);
    const int b_cl = ((lane >> 3) & 1) << 3;

#pragma unroll
    for (int k16 = 0; k16 < 64; k16 += 16) {
        uint32_t a0, a1, a2, a3;
        ldsm_x4(a0, a1, a2, a3, smem_u32(qs + a_rw * QS2 + k16 + a_cl));
        uint32_t bf[6][4];
#pragma unroll
        for (int jb = 0; jb < 6; jb++)
            ldsm_x4(bf[jb][0], bf[jb][1], bf[jb][2], bf[jb][3],
                    smem_u32(ks + (b_rw + jb * 16) * KS2 + k16 + b_cl));
#pragma unroll
        for (int jn = 0; jn < 12; jn++) {
            const int jb = jn >> 1, hf = (jn & 1) * 2;
            mma_f16(c[jn], a0, a1, a2, a3, bf[jb][hf], bf[jb][hf + 1]);
        }
    }

    const bool leftInv = (w == 0), rightInv = (w == NW - 1);
    if (leftInv || rightInv) {
#pragma unroll
        for (int jn = 0; jn < 12; jn++) {
            const int cb = wn * 96 + jn * 8 + (lane & 3) * 2;
#pragma unroll
            for (int e = 0; e < 4; e++) {
                const int jj = cb + (e & 1);
                if ((jj < 64 && leftInv) || (jj >= 128 && rightInv))
                    c[jn][e] = NEG_INF_F;
            }
        }
    }

    const int grA = wm * 16 + (lane >> 2);
    float mA = -1e30f, mB = -1e30f;
#pragma unroll
    for (int jn = 0; jn < 12; jn++) {
        mA = fmaxf(mA, fmaxf(c[jn][0], c[jn][1]));
        mB = fmaxf(mB, fmaxf(c[jn][2], c[jn][3]));
    }
    mA = fmaxf(mA, __shfl_xor_sync(0xffffffffu, mA, 1));
    mA = fmaxf(mA, __shfl_xor_sync(0xffffffffu, mA, 2));
    mB = fmaxf(mB, __shfl_xor_sync(0xffffffffu, mB, 1));
    mB = fmaxf(mB, __shfl_xor_sync(0xffffffffu, mB, 2));
    if ((lane & 3) == 0) {
        redbuf[wn * 64 + grA] = mA;
        redbuf[wn * 64 + grA + 8] = mB;
    }
    __syncthreads();
    mA = fmaxf(redbuf[grA], redbuf[64 + grA]);
    mB = fmaxf(redbuf[grA + 8], redbuf[64 + grA + 8]);

    float sA = 0.f, sB = 0.f;
#pragma unroll
    for (int jn = 0; jn < 12; jn++) {
        c[jn][0] = __expf(c[jn][0] - mA); sA += c[jn][0];
        c[jn][1] = __expf(c[jn][1] - mA); sA += c[jn][1];
        c[jn][2] = __expf(c[jn][2] - mB); sB += c[jn][2];
        c[jn][3] = __expf(c[jn][3] - mB); sB += c[jn][3];
    }
    sA += __shfl_xor_sync(0xffffffffu, sA, 1);
    sA += __shfl_xor_sync(0xffffffffu, sA, 2);
    sB += __shfl_xor_sync(0xffffffffu, sB, 1);
    sB += __shfl_xor_sync(0xffffffffu, sB, 2);
    if ((lane & 3) == 0) {
        sumbuf[wn * 64 + grA] = sA;
        sumbuf[wn * 64 + grA + 8] = sB;
    }
    __syncthreads();
    const float invA = 1.f / (sumbuf[grA] + sumbuf[64 + grA]);
    const float invB = 1.f / (sumbuf[grA + 8] + sumbuf[64 + grA + 8]);

    uint32_t ah[6][4], al[6][4];
#pragma unroll
    for (int kk = 0; kk < 6; kk++) {
        const int jn0 = 2 * kk, jn1 = 2 * kk + 1;
        float p00 = c[jn0][0] * invA, p01 = c[jn0][1] * invA;
        float p02 = c[jn0][2] * invB, p03 = c[jn0][3] * invB;
        float p10 = c[jn1][0] * invA, p11 = c[jn1][1] * invA;
        float p12 = c[jn1][2] * invB, p13 = c[jn1][3] * invB;
        ah[kk][0] = pack_h2(p00, p01);
        ah[kk][1] = pack_h2(p02, p03);
        ah[kk][2] = pack_h2(p10, p11);
        ah[kk][3] = pack_h2(p12, p13);
        __half2 h0 = *reinterpret_cast<__half2*>(&ah[kk][0]);
        __half2 h1 = *reinterpret_cast<__half2*>(&ah[kk][1]);
        __half2 h2 = *reinterpret_cast<__half2*>(&ah[kk][2]);
        __half2 h3 = *reinterpret_cast<__half2*>(&ah[kk][3]);
        al[kk][0] = pack_h2(p00 - __low2float(h0), p01 - __high2float(h0));
        al[kk][1] = pack_h2(p02 - __low2float(h1), p03 - __high2float(h1));
        al[kk][2] = pack_h2(p10 - __low2float(h2), p11 - __high2float(h2));
        al[kk][3] = pack_h2(p12 - __low2float(h3), p13 - __high2float(h3));
    }

    const int t_jofs = (((lane >> 3) & 1) << 3) + (lane & 7);
    const int t_eofs = (lane >> 4) << 3;
#pragma unroll
    for (int eh = 0; eh < 2; eh++) {
        float o[4][4];
#pragma unroll
        for (int jn = 0; jn < 4; jn++)
#pragma unroll
            for (int e = 0; e < 4; e++) o[jn][e] = 0.f;

#pragma unroll
        for (int kk = 0; kk < 6; kk++) {
            const int jcol = wn * 96 + kk * 16;
            uint32_t bf[2][4];
#pragma unroll
            for (int jb = 0; jb < 2; jb++)
                ldsm_x4_trans(bf[jb][0], bf[jb][1], bf[jb][2], bf[jb][3],
                              smem_u32(ks + (jcol + t_jofs) * KS2
                                       + eh * 32 + jb * 16 + t_eofs));
#pragma unroll
            for (int jn = 0; jn < 4; jn++) {
                const int jb = jn >> 1, hf = (jn & 1) * 2;
                mma_f16(o[jn], ah[kk][0], ah[kk][1], ah[kk][2], ah[kk][3],
                        bf[jb][hf], bf[jb][hf + 1]);
                mma_f16(o[jn], al[kk][0], al[kk][1], al[kk][2], al[kk][3],
                        bf[jb][hf], bf[jb][hf + 1]);
            }
        }

        if (wn == 0) {
#pragma unroll
            for (int jn = 0; jn < 4; jn++) {
                const int cb = jn * 8 + (lane & 3) * 2;
                oacc[grA * OA2 + cb] = o[jn][0];
                oacc[grA * OA2 + cb + 1] = o[jn][1];
                oacc[(grA + 8) * OA2 + cb] = o[jn][2];
                oacc[(grA + 8) * OA2 + cb + 1] = o[jn][3];
            }
        }
        __syncthreads();
        if (wn == 1) {
#pragma unroll
            for (int jn = 0; jn < 4; jn++) {
                const int cb = jn * 8 + (lane & 3) * 2;
#pragma unroll
                for (int half = 0; half < 2; half++) {
                    const int row = grA + half * 8;
                    const int n = w * M_ + row;
                    const int ecol = eh * 32 + cb;
                    const float v0 = o[jn][half * 2] + oacc[row * OA2 + cb];
                    const float v1 = o[jn][half * 2 + 1] + oacc[row * OA2 + cb + 1];
                    float* ad = attn_out +
                        ((size_t)(b * H_ + hh) * N_ + n) * D_ + ecol;
                    ad[0] = v0; ad[1] = v1;
                    *(__half2*)(g_attnH + ((size_t)b * N_ + n) * C_
                                + hh * D_ + ecol) = __floats2half2_rn(v0, v1);
                }
            }
        }
        __syncthreads();
    }
}

// ---------------- linear attention via mma (heads 4..7) ------------------------
// ctx = E^T V: 256 n-rows/block, 256 threads, fp16 kv input.
#define CXS 72
#define CTX_SMEM (2 * 256 * CXS * 2)     // et | vh = 73728 B

__global__ __launch_bounds__(256, 2) void ctx_mma_kernel()
{
    extern __shared__ __half smc[];
    __half* et = smc;                 // [256][CXS]
    __half* vh = et + 256 * CXS;

    const int bh = blockIdx.y;
    const int b = bh >> 2, hh4 = bh & 3;
    const int n0 = blockIdx.x * 256;
    const int t = threadIdx.x;
    const int warp = t >> 5, lane = t & 31;

    // fp16 loads: thread covers 8 fixed cols c8, rows r0 + 32k
    const __half* src = g_KVhL + ((size_t)b * N_ + n0) * 256 + hh4 * D_;
    const int c8 = (t & 7) * 8;
    const int r0 = t >> 3;            // 0..31
    float cs[8];
#pragma unroll
    for (int i = 0; i < 8; i++) cs[i] = 0.f;
#pragma unroll
    for (int k = 0; k < 8; k++) {
        const int r = r0 + k * 32;
        uint4 v = *(const uint4*)(src + (size_t)r * 256 + c8);
        *(uint4*)(vh + r * CXS + c8) = v;        // V tile: already fp16
        const __half* hv = (const __half*)&v;
        float e[8];
#pragma unroll
        for (int i = 0; i < 8; i++) {
            e[i] = __expf(__half2float(hv[i]));
            cs[i] += e[i];
        }
        __half* ep = et + r * CXS + c8;
        *(__half2*)(ep + 0) = __floats2half2_rn(e[0], e[1]);
        *(__half2*)(ep + 2) = __floats2half2_rn(e[2], e[3]);
        *(__half2*)(ep + 4) = __floats2half2_rn(e[4], e[5]);
        *(__half2*)(ep + 6) = __floats2half2_rn(e[6], e[7]);
    }
    // reduce csum across lanes sharing columns (lane, lane^8, lane^16, lane^24)
#pragma unroll
    for (int i = 0; i < 8; i++) {
        cs[i] += __shfl_xor_sync(0xffffffffu, cs[i], 8);
        cs[i] += __shfl_xor_sync(0xffffffffu, cs[i], 16);
    }
    if ((lane >> 3) == 0) {
#pragma unroll
        for (int i = 0; i < 8; i++)
            atomicAdd(&g_csum[bh * 64 + c8 + i], cs[i]);
    }
    __syncthreads();

    // warps 0-3: k-rows 0-127; warps 4-7: 128-255. m-tile (warp&3)*16.
    const int kbase = (warp >> 2) * 128;
    const int m0 = (warp & 3) * 16;
    float acc[8][4];
#pragma unroll
    for (int jn = 0; jn < 8; jn++)
#pragma unroll
        for (int e = 0; e < 4; e++) acc[jn][e] = 0.f;

    const int a_r = ((lane >> 4) << 3) + (lane & 7);
    const int a_c = m0 + (((lane >> 3) & 1) << 3);
    const int b_r = (((lane >> 3) & 1) << 3) + (lane & 7);
    const int b_cofs = (lane >> 4) << 3;

#pragma unroll
    for (int kc = 0; kc < 8; kc++) {
        const int k0 = kbase + kc * 16;
        uint32_t a0, a1, a2, a3;
        ldsm_x4_trans(a0, a1, a2, a3, smem_u32(et + (k0 + a_r) * CXS + a_c));
        uint32_t bf[4][4];
#pragma unroll
        for (int jb = 0; jb < 4; jb++)
            ldsm_x4_trans(bf[jb][0], bf[jb][1], bf[jb][2], bf[jb][3],
                          smem_u32(vh + (k0 + b_r) * CXS + jb * 16 + b_cofs));
#pragma unroll
        for (int jn = 0; jn < 8; jn++) {
            const int jb = jn >> 1, hf = (jn & 1) * 2;
            mma_f16(acc[jn], a0, a1, a2, a3, bf[jb][hf], bf[jb][hf + 1]);
        }
    }

    float* cdst = g_ctx + bh * 4096;
    const int d0 = m0 + (lane >> 2);
#pragma unroll
    for (int jn = 0; jn < 8; jn++) {
        const int e0 = jn * 8 + (lane & 3) * 2;
        atomicAdd(&cdst[d0 * 64 + e0], acc[jn][0]);
        atomicAdd(&cdst[d0 * 64 + e0 + 1], acc[jn][1]);
        atomicAdd(&cdst[(d0 + 8) * 64 + e0], acc[jn][2]);
        atomicAdd(&cdst[(d0 + 8) * 64 + e0 + 1], acc[jn][3]);
    }
}

// lin_out: out = softmax(q) @ (ctx * 0.125/csum[d]); softq and ctx as exact hi/lo
#define LO_CTS 72
#define LO_SQS 136
#define LO_OFF_CTH 0
#define LO_OFF_CTL (LO_OFF_CTH + 64 * LO_CTS * 2)    // 9216
#define LO_OFF_SQ  (LO_OFF_CTL + 64 * LO_CTS * 2)    // 18432
#define LO_OFF_CI  (LO_OFF_SQ + 64 * LO_SQS * 2)     // 35840
#define LO_SMEM    (LO_OFF_CI + 256)                 // 36096

__global__ __launch_bounds__(128) void lin_out_mma(float* __restrict__ attn_out)
{
    extern __shared__ char sml[];
    __half* cth = (__half*)(sml + LO_OFF_CTH);
    __half* ctl = (__half*)(sml + LO_OFF_CTL);
    __half* sq = (__half*)(sml + LO_OFF_SQ);
    float* cinv_s = (float*)(sml + LO_OFF_CI);

    const int bh = blockIdx.y;
    const int b = bh >> 2, hh4 = bh & 3, hh = 4 + hh4;
    const int t = threadIdx.x;
    const int warp = t >> 5, lane = t & 31;

    if (t < 64) cinv_s[t] = 0.125f / g_csum[bh * 64 + t];
    __syncthreads();

    for (int idx = t; idx < 4096; idx += 128) {
        const int d = idx >> 6, e = idx & 63;
        float v = g_ctx[bh * 4096 + idx] * cinv_s[d];
        __half h = __float2half_rn(v);
        cth[d * LO_CTS + e] = h;
        ctl[d * LO_CTS + e] = __float2half_rn(v - __half2float(h));
    }

    for (int r = warp; r < 64; r += 4) {
        const int n = blockIdx.x * 64 + r;
        const __half* qrow = g_QhL + ((size_t)b * N_ + n) * 256 + hh4 * D_;
        float q0 = __half2float(qrow[lane]);
        float q1 = __half2float(qrow[lane + 32]);
        float m = fmaxf(q0, q1);
#pragma unroll
        for (int o = 16; o; o >>= 1) m = fmaxf(m, __shfl_xor_sync(0xffffffffu, m, o));
        float e0 = __expf(q0 - m), e1 = __expf(q1 - m);
        float s = e0 + e1;
#pragma unroll
        for (int o = 16; o; o >>= 1) s += __shfl_xor_sync(0xffffffffu, s, o);
        float inv = 1.f / s;
        float p0 = e0 * inv, p1 = e1 * inv;
        __half h0 = __float2half_rn(p0), h1 = __float2half_rn(p1);
        sq[r * LO_SQS + lane] = h0;
        sq[r * LO_SQS + lane + 32] = h1;
        sq[r * LO_SQS + 64 + lane] = __float2half_rn(p0 - __half2float(h0));
        sq[r * LO_SQS + 64 + lane + 32] = __float2half_rn(p1 - __half2float(h1));
    }
    __syncthreads();

    float o[8][4];
#pragma unroll
    for (int jn = 0; jn < 8; jn++)
#pragma unroll
        for (int e = 0; e < 4; e++) o[jn][e] = 0.f;

    const int a_row = warp * 16 + (lane & 15);
    const int a_cofs = (lane >> 4) << 3;
    const int b_r = (((lane >> 3) & 1) << 3) + (lane & 7);
    const int b_cofs = (lane >> 4) << 3;

#pragma unroll
    for (int kc = 0; kc < 8; kc++) {
        const int k16 = kc * 16;
        uint32_t a0, a1, a2, a3;
        ldsm_x4(a0, a1, a2, a3, smem_u32(sq + a_row * LO_SQS + k16 + a_cofs));
        const __half* Bt = (k16 < 64) ? cth : ctl;
        const int kd = k16 & 63;
        uint32_t bf[4][4];
#pragma unroll
        for (int jb = 0; jb < 4; jb++)
            ldsm_x4_trans(bf[jb][0], bf[jb][1], bf[jb][2], bf[jb][3],
                          smem_u32(Bt + (kd + b_r) * LO_CTS + jb * 16 + b_cofs));
#pragma unroll
        for (int jn = 0; jn < 8; jn++) {
            const int jb = jn >> 1, hf = (jn & 1) * 2;
            mma_f16(o[jn], a0, a1, a2, a3, bf[jb][hf], bf[jb][hf + 1]);
        }
    }

#pragma unroll
    for (int jn = 0; jn < 8; jn++) {
        const int e0 = jn * 8 + (lane & 3) * 2;
#pragma unroll
        for (int half = 0; half < 2; half++) {
            const int row = warp * 16 + (lane >> 2) + half * 8;
            const int n = blockIdx.x * 64 + row;
            const float v0 = o[jn][half * 2], v1 = o[jn][half * 2 + 1];
            float* ad = attn_out + ((size_t)(b * H_ + hh) * N_ + n) * D_ + e0;
            ad[0] = v0; ad[1] = v1;
            *(__half2*)(g_attnH + ((size_t)b * N_ + n) * C_ + hh * D_ + e0) =
                __floats2half2_rn(v0, v1);
        }
    }
}

// ---------------------------------- launch ------------------------------------
extern "C" void kernel_launch(void* const* d_in, const int* in_sizes, int n_in,
                              void* d_out, int out_size)
{
    (void)in_sizes; (void)n_in; (void)out_size;
    const float* x     = (const float*)d_in[0];
    const float* Wq    = (const float*)d_in[1];
    const float* Wkv   = (const float*)d_in[2];
    const float* Wproj = (const float*)d_in[3];
    const float* bproj = (const float*)d_in[4];

    float* y    = (float*)d_out;
    float* attn = y + (size_t)ROWS * C_;

    __half *pxh, *paH, *pW16, *pWp16, *pQh, *pKVh, *pQhL, *pKVhL;
    cudaGetSymbolAddress((void**)&pQh, g_Qh);
    cudaGetSymbolAddress((void**)&pKVh, g_KVh);
    cudaGetSymbolAddress((void**)&pQhL, g_QhL);
    cudaGetSymbolAddress((void**)&pKVhL, g_KVhL);
    cudaGetSymbolAddress((void**)&pxh, g_xh);
    cudaGetSymbolAddress((void**)&paH, g_attnH);
    cudaGetSymbolAddress((void**)&pW16, g_W16);
    cudaGetSymbolAddress((void**)&pWp16, g_Wp16);

    cudaFuncSetAttribute(gemm_f16,
                         cudaFuncAttributeMaxDynamicSharedMemorySize, GEMM_SMEM);
    cudaFuncSetAttribute(local_attn_mma,
                         cudaFuncAttributeMaxDynamicSharedMemorySize, LA_SMEM);
    cudaFuncSetAttribute(ctx_mma_kernel,
                         cudaFuncAttributeMaxDynamicSharedMemorySize, CTX_SMEM);
    cudaFuncSetAttribute(lin_out_mma,
                         cudaFuncAttributeMaxDynamicSharedMemorySize, LO_SMEM);

    static cudaStream_t s2 = nullptr;
    static cudaEvent_t eFork0 = nullptr, eJoin0 = nullptr;
    static cudaEvent_t eFork1 = nullptr, eJoin1 = nullptr;
    if (!s2) {
        cudaStreamCreateWithFlags(&s2, cudaStreamNonBlocking);
        cudaEventCreateWithFlags(&eFork0, cudaEventDisableTiming);
        cudaEventCreateWithFlags(&eJoin0, cudaEventDisableTiming);
        cudaEventCreateWithFlags(&eFork1, cudaEventDisableTiming);
        cudaEventCreateWithFlags(&eJoin1, cudaEventDisableTiming);
    }

    // fork: x conversion on s2, weight prep + ctx zeroing on main
    cudaEventRecord(eFork0, 0);
    cudaStreamWaitEvent(s2, eFork0, 0);
    round_h_kernel<<<2048, 256, 0, s2>>>(x, pxh, ROWS);
    cudaEventRecord(eJoin0, s2);
    prep_kernel<<<512, 256>>>(Wq, Wkv, Wproj);
    cudaStreamWaitEvent(0, eJoin0, 0);

    // fused Q+KV GEMM: n-tiles -> Qh | QhL | KVh | KVhL (all fp16)
    gemm_f16<<<dim3(4, ROWS / 128), 512, GEMM_SMEM>>>(
        pxh, pW16, nullptr, pQh, pQhL, pKVh, pKVhL, nullptr, 0);

    // fork: local heads on main, linear heads on s2
    cudaEventRecord(eFork1, 0);
    cudaStreamWaitEvent(s2, eFork1, 0);
    ctx_mma_kernel<<<dim3(32, 16), 256, CTX_SMEM, s2>>>();
    lin_out_mma<<<dim3(128, 16), 128, LO_SMEM, s2>>>(attn);
    cudaEventRecord(eJoin1, s2);

    local_attn_mma<<<dim3(NW, 16), 256, LA_SMEM>>>(attn);
    cudaStreamWaitEvent(0, eJoin1, 0);

    // proj GEMM: y = attnH @ Wp16^T + bias
    gemm_f16<<<dim3(2, ROWS / 128), 512, GEMM_SMEM>>>(
        paH, pWp16, y, nullptr, nullptr, nullptr, nullptr, bproj, 1);
}